// round 4
// baseline (speedup 1.0000x reference)
#include <cuda_runtime.h>
#include <math.h>
#include <stdint.h>

#define NTOK 8192
#define DDIM 1024
#define FDIM 2816
#define NEXP 8
#define CAP  8192

// ---------------- device scratch ----------------
__device__ int   g_count[NEXP];
__device__ int   g_tok[NEXP * CAP];
__device__ int   g_slot[NTOK * 2];
__device__ float g_wt[NTOK * 2];
__device__ float g_act[(size_t)NEXP * CAP * FDIM];
__device__ float g_y[(size_t)NEXP * CAP * DDIM];

// ---------------- helpers ----------------
__device__ __forceinline__ uint32_t smem_u32(const void* p) {
    uint32_t a;
    asm("{ .reg .u64 t; cvta.to.shared.u64 t, %1; cvt.u32.u64 %0, t; }" : "=r"(a) : "l"(p));
    return a;
}
__device__ __forceinline__ uint32_t cvt_tf32(float x) {
    uint32_t r; asm("cvt.rna.tf32.f32 %0, %1;" : "=r"(r) : "f"(x)); return r;
}

#define CPA(dst, src, n) asm volatile("cp.async.cg.shared.global [%0], [%1], 16, %2;" :: "r"(dst), "l"(src), "r"(n) : "memory")
#define CPA_COMMIT()     asm volatile("cp.async.commit_group;" ::: "memory")
#define CPA_WAIT1()      asm volatile("cp.async.wait_group 1;" ::: "memory")

#define MMA_TF32(d, a, b) \
    asm volatile("mma.sync.aligned.m16n8k8.row.col.f32.tf32.tf32.f32 " \
        "{%0,%1,%2,%3}, {%4,%5,%6,%7}, {%8,%9}, {%0,%1,%2,%3};" \
        : "+f"((d)[0]), "+f"((d)[1]), "+f"((d)[2]), "+f"((d)[3]) \
        : "r"((a)[0]), "r"((a)[1]), "r"((a)[2]), "r"((a)[3]), "r"((b)[0]), "r"((b)[1]))

// ---------------- kernel 0: reset ----------------
__global__ void reset_kernel() {
    if (threadIdx.x < NEXP) g_count[threadIdx.x] = 0;
}

// ---------------- kernel 1: router ----------------
__global__ void router_kernel(const float* __restrict__ X, const float* __restrict__ RW) {
    __shared__ float sW[NEXP * DDIM];
    const int tid = threadIdx.x;
    for (int i = tid; i < NEXP * DDIM; i += 128) {
        int d = i >> 3, e = i & 7;
        sW[e * DDIM + d] = RW[i];
    }
    __syncthreads();
    const int warp = tid >> 5, lane = tid & 31;
    const int t = blockIdx.x * 4 + warp;
    const float* xr = X + (size_t)t * DDIM;
    float acc[NEXP];
#pragma unroll
    for (int e = 0; e < NEXP; e++) acc[e] = 0.f;
    for (int d = lane; d < DDIM; d += 32) {
        float xv = xr[d];
#pragma unroll
        for (int e = 0; e < NEXP; e++) acc[e] += xv * sW[e * DDIM + d];
    }
#pragma unroll
    for (int e = 0; e < NEXP; e++)
#pragma unroll
        for (int off = 16; off > 0; off >>= 1)
            acc[e] += __shfl_xor_sync(0xFFFFFFFFu, acc[e], off);
    if (lane == 0) {
        int i0 = 0; float s0 = acc[0];
#pragma unroll
        for (int e = 1; e < NEXP; e++) if (acc[e] > s0) { s0 = acc[e]; i0 = e; }
        int i1 = -1; float s1 = -INFINITY;
#pragma unroll
        for (int e = 0; e < NEXP; e++) if (e != i0 && acc[e] > s1) { s1 = acc[e]; i1 = e; }
        float w0 = 1.f / (1.f + expf(s1 - s0));
        float w1 = 1.f - w0;
        int p0 = atomicAdd(&g_count[i0], 1);
        int p1 = atomicAdd(&g_count[i1], 1);
        g_tok[i0 * CAP + p0] = t;
        g_tok[i1 * CAP + p1] = t;
        g_slot[2 * t + 0] = i0 * CAP + p0;  g_wt[2 * t + 0] = w0;
        g_slot[2 * t + 1] = i1 * CAP + p1;  g_wt[2 * t + 1] = w1;
    }
}

// ================= tf32 mma.sync GEMMs =================

// ---------------- kernel 2: fused gate+up + SiLU ----------------
// CTA 128x128x32, 8 warps (2M x 4N), warp 64x32 for BOTH gate and up.
__global__ void __launch_bounds__(256, 1)
gateup_mma_kernel(const float* __restrict__ X,
                  const float* __restrict__ Wg,
                  const float* __restrict__ Wu) {
    extern __shared__ float smem[];
    float* As  = smem;              // 3 * 4096
    float* Bgs = smem + 12288;      // 3 * 4096
    float* Bus = smem + 24576;      // 3 * 4096

    const int e = blockIdx.z;
    const int cnt = g_count[e];
    const int m0 = blockIdx.x * 128;
    if (m0 >= cnt) return;
    const int n0 = blockIdx.y * 128;

    const int tid = threadIdx.x, wid = tid >> 5, lane = tid & 31;
    const int wm = wid & 1, wn = wid >> 1;
    const int lr = lane >> 2, lc = lane & 3;

    // A gmem->smem: thread -> row tid>>1, 4 chunks of 16B along k
    const int ar = tid >> 1;
    const bool av = (m0 + ar) < cnt;
    const float* arow = X + (size_t)(av ? g_tok[e * CAP + m0 + ar] : 0) * DDIM;
    const int an = av ? 16 : 0;
    uint32_t aoff[4]; int ac[4];
#pragma unroll
    for (int i = 0; i < 4; i++) {
        int c = (tid & 1) * 4 + i;
        ac[i] = c;
        aoff[i] = (uint32_t)(ar * 128 + ((c ^ (ar & 7)) << 4));
    }
    // B gmem->smem: thread -> k-row tid>>3, 4 chunks of 16B along n (128 floats)
    const int bk = tid >> 3;
    const float* grow = Wg + ((size_t)e * DDIM + bk) * FDIM + n0;
    const float* urow = Wu + ((size_t)e * DDIM + bk) * FDIM + n0;
    uint32_t boff[4]; int bc[4];
#pragma unroll
    for (int i = 0; i < 4; i++) {
        int c = (tid & 7) + 8 * i;
        bc[i] = c;
        boff[i] = (uint32_t)(bk * 512 + ((c ^ ((bk & 3) << 1)) << 4));
    }

    const uint32_t sA = smem_u32(As), sG = smem_u32(Bgs), sU = smem_u32(Bus);

    float accg[4][4][4], accu[4][4][4];
#pragma unroll
    for (int mi = 0; mi < 4; mi++)
#pragma unroll
        for (int ni = 0; ni < 4; ni++)
#pragma unroll
            for (int q = 0; q < 4; q++) { accg[mi][ni][q] = 0.f; accu[mi][ni][q] = 0.f; }

    const int KT = DDIM / 32;   // 32

#define GU_PREFETCH(s) do { \
    int _buf = (s) % 3; \
    uint32_t _da = sA + _buf * 16384, _dg = sG + _buf * 16384, _du = sU + _buf * 16384; \
    const float* _ap = arow + (s) * 32; \
    const float* _gp = grow + (size_t)(s) * 32 * FDIM; \
    const float* _up = urow + (size_t)(s) * 32 * FDIM; \
    _Pragma("unroll") \
    for (int _i = 0; _i < 4; _i++) { \
        CPA(_da + aoff[_i], _ap + ac[_i] * 4, an); \
        CPA(_dg + boff[_i], _gp + bc[_i] * 4, 16); \
        CPA(_du + boff[_i], _up + bc[_i] * 4, 16); \
    } } while (0)

    GU_PREFETCH(0); CPA_COMMIT();
    GU_PREFETCH(1); CPA_COMMIT();

    for (int s = 0; s < KT; s++) {
        CPA_WAIT1();
        __syncthreads();
        if (s + 2 < KT) { GU_PREFETCH(s + 2); }
        CPA_COMMIT();
        const int buf = s % 3;
        const float* A = As  + buf * 4096;
        const float* G = Bgs + buf * 4096;
        const float* U = Bus + buf * 4096;
#pragma unroll
        for (int k8 = 0; k8 < 4; k8++) {
            uint32_t a[4][4];
#pragma unroll
            for (int mi = 0; mi < 4; mi++) {
                const int r0 = wm * 64 + mi * 16 + lr;
#pragma unroll
                for (int h = 0; h < 2; h++) {
                    const int cx = (((2 * k8 + h) ^ lr) << 2) + lc;
                    a[mi][h * 2 + 0] = cvt_tf32(A[r0 * 32 + cx]);
                    a[mi][h * 2 + 1] = cvt_tf32(A[(r0 + 8) * 32 + cx]);
                }
            }
#pragma unroll
            for (int ni = 0; ni < 4; ni++) {
                const int c = wn * 8 + ni * 2 + (lr >> 2);
                const int bx = ((c ^ (lc << 1)) << 2) + (lr & 3);
                uint32_t bg[2], bu[2];
#pragma unroll
                for (int h = 0; h < 2; h++) {
                    const int off = (k8 * 8 + lc + 4 * h) * 128 + bx;
                    bg[h] = cvt_tf32(G[off]);
                    bu[h] = cvt_tf32(U[off]);
                }
#pragma unroll
                for (int mi = 0; mi < 4; mi++) {
                    MMA_TF32(accg[mi][ni], a[mi], bg);
                    MMA_TF32(accu[mi][ni], a[mi], bu);
                }
            }
        }
    }

    // epilogue: silu(g)*u, direct float2 stores
#pragma unroll
    for (int mi = 0; mi < 4; mi++) {
        const int r = wm * 64 + mi * 16 + lr;
        const size_t row0 = (size_t)e * CAP + m0 + r;
#pragma unroll
        for (int ni = 0; ni < 4; ni++) {
            const int col = n0 + wn * 32 + ni * 8 + 2 * lc;
            if (m0 + r < cnt) {
                float g0 = accg[mi][ni][0], g1 = accg[mi][ni][1];
                float2 v;
                v.x = (g0 / (1.f + __expf(-g0))) * accu[mi][ni][0];
                v.y = (g1 / (1.f + __expf(-g1))) * accu[mi][ni][1];
                *(float2*)&g_act[row0 * FDIM + col] = v;
            }
            if (m0 + r + 8 < cnt) {
                float g2 = accg[mi][ni][2], g3 = accg[mi][ni][3];
                float2 v;
                v.x = (g2 / (1.f + __expf(-g2))) * accu[mi][ni][2];
                v.y = (g3 / (1.f + __expf(-g3))) * accu[mi][ni][3];
                *(float2*)&g_act[(row0 + 8) * FDIM + col] = v;
            }
        }
    }
}

// ---------------- kernel 3: down GEMM ----------------
// CTA 128x256x32, 8 warps (2M x 4N), warp tile 64x64.
// A smem: [m][k] 128x32, chunk swizzle c^=(r&7).
// B smem: [k][n] 32x256 (row 1024B, 64 chunks), chunk swizzle c^=2*(k&3).
__global__ void __launch_bounds__(256, 1)
down_mma_kernel(const float* __restrict__ Wd) {
    extern __shared__ float smem[];
    float* As = smem;               // 3 * 4096 floats
    float* Bs = smem + 12288;       // 3 * 8192 floats

    const int e = blockIdx.z;
    const int cnt = g_count[e];
    const int m0 = blockIdx.x * 128;
    if (m0 >= cnt) return;
    const int n0 = blockIdx.y * 256;

    const int tid = threadIdx.x, wid = tid >> 5, lane = tid & 31;
    const int wm = wid & 1, wn = wid >> 1;   // wn in 0..3, 64-col slabs
    const int lr = lane >> 2, lc = lane & 3;

    const int ar = tid >> 1;
    const bool av = (m0 + ar) < cnt;
    const float* arow = g_act + ((size_t)e * CAP + m0 + (av ? ar : 0)) * FDIM;
    const int an = av ? 16 : 0;
    uint32_t aoff[4]; int ac[4];
#pragma unroll
    for (int i = 0; i < 4; i++) {
        int c = (tid & 1) * 4 + i;
        ac[i] = c;
        aoff[i] = (uint32_t)(ar * 128 + ((c ^ (ar & 7)) << 4));
    }
    // B: thread -> k-row tid>>3 (0..31), 8 chunks along n (256 floats = 64 chunks)
    const int bk = tid >> 3;
    const float* brow = Wd + ((size_t)e * FDIM + bk) * DDIM + n0;
    uint32_t boff[8]; int bc[8];
#pragma unroll
    for (int i = 0; i < 8; i++) {
        int c = (tid & 7) + 8 * i;
        bc[i] = c;
        boff[i] = (uint32_t)(bk * 1024 + ((c ^ ((bk & 3) << 1)) << 4));
    }

    const uint32_t sA = smem_u32(As), sB = smem_u32(Bs);

    float acc[4][8][4];
#pragma unroll
    for (int mi = 0; mi < 4; mi++)
#pragma unroll
        for (int ni = 0; ni < 8; ni++)
#pragma unroll
            for (int q = 0; q < 4; q++) acc[mi][ni][q] = 0.f;

    const int KT = FDIM / 32;   // 88

#define DN_PREFETCH(s) do { \
    int _buf = (s) % 3; \
    uint32_t _da = sA + _buf * 16384, _db = sB + _buf * 32768; \
    const float* _ap = arow + (s) * 32; \
    const float* _bp = brow + (size_t)(s) * 32 * DDIM; \
    _Pragma("unroll") \
    for (int _i = 0; _i < 4; _i++) CPA(_da + aoff[_i], _ap + ac[_i] * 4, an); \
    _Pragma("unroll") \
    for (int _i = 0; _i < 8; _i++) CPA(_db + boff[_i], _bp + bc[_i] * 4, 16); \
    } while (0)

    DN_PREFETCH(0); CPA_COMMIT();
    DN_PREFETCH(1); CPA_COMMIT();

    for (int s = 0; s < KT; s++) {
        CPA_WAIT1();
        __syncthreads();
        if (s + 2 < KT) { DN_PREFETCH(s + 2); }
        CPA_COMMIT();
        const int buf = s % 3;
        const float* A = As + buf * 4096;
        const float* B = Bs + buf * 8192;
#pragma unroll
        for (int k8 = 0; k8 < 4; k8++) {
            uint32_t a[4][4];
#pragma unroll
            for (int mi = 0; mi < 4; mi++) {
                const int r0 = wm * 64 + mi * 16 + lr;
#pragma unroll
                for (int h = 0; h < 2; h++) {
                    const int cx = (((2 * k8 + h) ^ lr) << 2) + lc;
                    a[mi][h * 2 + 0] = cvt_tf32(A[r0 * 32 + cx]);
                    a[mi][h * 2 + 1] = cvt_tf32(A[(r0 + 8) * 32 + cx]);
                }
            }
#pragma unroll
            for (int ni = 0; ni < 8; ni++) {
                const int cidx = wn * 16 + ni * 2 + (lr >> 2);
                const int bx = ((cidx ^ (lc << 1)) << 2) + (lr & 3);
                uint32_t b[2];
#pragma unroll
                for (int h = 0; h < 2; h++)
                    b[h] = cvt_tf32(B[(k8 * 8 + lc + 4 * h) * 256 + bx]);
#pragma unroll
                for (int mi = 0; mi < 4; mi++)
                    MMA_TF32(acc[mi][ni], a[mi], b);
            }
        }
    }

#pragma unroll
    for (int mi = 0; mi < 4; mi++) {
        const int r = wm * 64 + mi * 16 + lr;
        const size_t row0 = (size_t)e * CAP + m0 + r;
#pragma unroll
        for (int ni = 0; ni < 8; ni++) {
            const int col = n0 + wn * 64 + ni * 8 + 2 * lc;
            if (m0 + r < cnt) {
                float2 v; v.x = acc[mi][ni][0]; v.y = acc[mi][ni][1];
                *(float2*)&g_y[row0 * DDIM + col] = v;
            }
            if (m0 + r + 8 < cnt) {
                float2 v; v.x = acc[mi][ni][2]; v.y = acc[mi][ni][3];
                *(float2*)&g_y[(row0 + 8) * DDIM + col] = v;
            }
        }
    }
}

// ---------------- kernel 4: weighted combine ----------------
__global__ void combine_kernel(float* __restrict__ out) {
    const int g = blockIdx.x * blockDim.x + threadIdx.x;
    const int t = g >> 8;
    const int c = g & 255;
    const int s0 = g_slot[2 * t], s1 = g_slot[2 * t + 1];
    const float w0 = g_wt[2 * t], w1 = g_wt[2 * t + 1];
    const float4* Y = (const float4*)g_y;
    float4 a = Y[(size_t)s0 * 256 + c];
    float4 b = Y[(size_t)s1 * 256 + c];
    float4 o;
    o.x = w0 * a.x + w1 * b.x;
    o.y = w0 * a.y + w1 * b.y;
    o.z = w0 * a.z + w1 * b.z;
    o.w = w0 * a.w + w1 * b.w;
    ((float4*)out)[g] = o;
}

// ---------------- launch ----------------
extern "C" void kernel_launch(void* const* d_in, const int* in_sizes, int n_in,
                              void* d_out, int out_size) {
    const float* x  = (const float*)d_in[0];
    const float* rw = (const float*)d_in[1];
    const float* wg = (const float*)d_in[2];
    const float* wu = (const float*)d_in[3];
    const float* wd = (const float*)d_in[4];
    float* out = (float*)d_out;

    cudaFuncSetAttribute(gateup_mma_kernel, cudaFuncAttributeMaxDynamicSharedMemorySize, 147456);
    cudaFuncSetAttribute(down_mma_kernel,   cudaFuncAttributeMaxDynamicSharedMemorySize, 147456);

    reset_kernel<<<1, 32>>>();
    router_kernel<<<NTOK / 4, 128>>>(x, rw);

    gateup_mma_kernel<<<dim3(CAP / 128, FDIM / 128, NEXP), 256, 147456>>>(x, wg, wu);
    down_mma_kernel<<<dim3(CAP / 128, DDIM / 256, NEXP), 256, 147456>>>(wd);

    combine_kernel<<<(NTOK * 256) / 256, 256>>>(out);
}